// round 1
// baseline (speedup 1.0000x reference)
#include <cuda_runtime.h>
#include <math.h>

#define Bsz 8
#define Ssz 2048
#define Fsz 256
#define Dsz 256

// Scratch for Q/K/V projections (alloc-free rule: __device__ globals)
__device__ float g_Q[Bsz * Ssz * Dsz];
__device__ float g_K[Bsz * Ssz * Dsz];
__device__ float g_V[Bsz * Ssz * Dsz];

// ---------------------------------------------------------------------------
// Kernel 1: fused QKV projection. Y = x @ W + b for W in {Wq,Wk,Wv} (blockIdx.z)
// Tiled GEMM: BM=64, BN=64, BK=16, 256 threads, 4x4 micro-tile per thread.
// ---------------------------------------------------------------------------
#define PBM 64
#define PBN 64
#define PBK 16

__global__ __launch_bounds__(256) void qkv_proj_kernel(
    const float* __restrict__ x,
    const float* __restrict__ Wq, const float* __restrict__ bq,
    const float* __restrict__ Wk, const float* __restrict__ bk,
    const float* __restrict__ Wv, const float* __restrict__ bv)
{
    const float* W;
    const float* bias;
    float* Y;
    if (blockIdx.z == 0)      { W = Wq; bias = bq; Y = g_Q; }
    else if (blockIdx.z == 1) { W = Wk; bias = bk; Y = g_K; }
    else                      { W = Wv; bias = bv; Y = g_V; }

    __shared__ float As[PBK][68];   // A transposed, padded (store conflicts)
    __shared__ float Bs[PBK][64];

    const int tid = threadIdx.x;
    const int m0 = blockIdx.x * PBM;
    const int n0 = blockIdx.y * PBN;
    const int ty = tid >> 4, tx = tid & 15;

    const int ra = tid >> 2, cq = (tid & 3) * 4;   // A loader
    const int kb = tid >> 4, nb = (tid & 15) * 4;  // B loader

    float acc[4][4];
#pragma unroll
    for (int i = 0; i < 4; i++)
#pragma unroll
        for (int j = 0; j < 4; j++) acc[i][j] = 0.f;

    for (int k0 = 0; k0 < Fsz; k0 += PBK) {
        float4 a = *(const float4*)(x + (size_t)(m0 + ra) * Fsz + k0 + cq);
        As[cq + 0][ra] = a.x; As[cq + 1][ra] = a.y;
        As[cq + 2][ra] = a.z; As[cq + 3][ra] = a.w;
        *(float4*)&Bs[kb][nb] =
            *(const float4*)(W + (size_t)(k0 + kb) * Dsz + n0 + nb);
        __syncthreads();

#pragma unroll
        for (int k = 0; k < PBK; k++) {
            float4 av  = *(const float4*)&As[k][ty * 4];
            float4 bv4 = *(const float4*)&Bs[k][tx * 4];
            float aa[4] = {av.x, av.y, av.z, av.w};
            float bb[4] = {bv4.x, bv4.y, bv4.z, bv4.w};
#pragma unroll
            for (int i = 0; i < 4; i++)
#pragma unroll
                for (int j = 0; j < 4; j++) acc[i][j] += aa[i] * bb[j];
        }
        __syncthreads();
    }

#pragma unroll
    for (int i = 0; i < 4; i++) {
        float4 o;
        o.x = acc[i][0] + bias[n0 + tx * 4 + 0];
        o.y = acc[i][1] + bias[n0 + tx * 4 + 1];
        o.z = acc[i][2] + bias[n0 + tx * 4 + 2];
        o.w = acc[i][3] + bias[n0 + tx * 4 + 3];
        *(float4*)(Y + (size_t)(m0 + ty * 4 + i) * Dsz + n0 + tx * 4) = o;
    }
}

// ---------------------------------------------------------------------------
// Kernel 2: flash attention. One CTA = (batch b, 64-row q tile). 256 threads.
// Q/K/V tiles in smem (padded rows to break 1024B-stride bank aliasing),
// online softmax, O accumulator in registers (64 f32/thread).
// ---------------------------------------------------------------------------
#define QTILE 64
#define KTILE 64
#define LDQ   260   // 256 + 4 pad (1040B rows -> 16B/row bank shift)
#define LDSS  68    // 64 + 4 pad
#define ATTN_SMEM_BYTES ((3 * 64 * LDQ + 64 * LDSS) * 4)  // 217088

__global__ __launch_bounds__(256) void attn_kernel(float* __restrict__ out)
{
    extern __shared__ float sm[];
    float* Qs = sm;                 // [64][LDQ]
    float* Ks = Qs + 64 * LDQ;      // [64][LDQ]
    float* Vs = Ks + 64 * LDQ;      // [64][LDQ]
    float* Ss = Vs + 64 * LDQ;      // [64][LDSS]

    const int b  = blockIdx.y;
    const int q0 = blockIdx.x * QTILE;
    const int tid = threadIdx.x;

    const float* Qg = g_Q + ((size_t)b * Ssz + q0) * Dsz;
    const float* Kg = g_K + (size_t)b * Ssz * Dsz;
    const float* Vg = g_V + (size_t)b * Ssz * Dsz;

    // Load Q tile (64 x 256 floats = 4096 float4, 16 per thread)
    for (int i = tid; i < QTILE * (Dsz / 4); i += 256) {
        int r = i >> 6;              // 64 float4 per row
        int c = (i & 63) * 4;
        *(float4*)&Qs[r * LDQ + c] = *(const float4*)(Qg + r * Dsz + c);
    }

    // S-compute mapping: strided 4x4 micro-tile (rows ty+16i, cols tx+16j)
    const int ty = tid >> 4, tx = tid & 15;
    // softmax / AV mapping: thread owns row rr, column segment c0..c0+63
    const int rr = tid >> 2, qq = tid & 3;
    const int c0 = qq * 64;

    float o[64];
#pragma unroll
    for (int i = 0; i < 64; i++) o[i] = 0.f;
    float mrow = -1e30f, lrow = 0.f;

    for (int j0 = 0; j0 < Ssz; j0 += KTILE) {
        __syncthreads();  // prev AV done (and Q load done on first iter)

        // Load K/V tiles
        for (int i = tid; i < KTILE * 64; i += 256) {
            int r = i >> 6;
            int c = (i & 63) * 4;
            *(float4*)&Ks[r * LDQ + c] = *(const float4*)(Kg + (size_t)(j0 + r) * Dsz + c);
            *(float4*)&Vs[r * LDQ + c] = *(const float4*)(Vg + (size_t)(j0 + r) * Dsz + c);
        }
        __syncthreads();

        // S = (Q @ K^T) / 16
        float acc[4][4];
#pragma unroll
        for (int i = 0; i < 4; i++)
#pragma unroll
            for (int j = 0; j < 4; j++) acc[i][j] = 0.f;

        for (int k4 = 0; k4 < Dsz / 4; k4++) {
            float4 qv[4], kv[4];
#pragma unroll
            for (int i = 0; i < 4; i++)
                qv[i] = *(const float4*)&Qs[(ty + 16 * i) * LDQ + k4 * 4];
#pragma unroll
            for (int j = 0; j < 4; j++)
                kv[j] = *(const float4*)&Ks[(tx + 16 * j) * LDQ + k4 * 4];
#pragma unroll
            for (int i = 0; i < 4; i++)
#pragma unroll
                for (int j = 0; j < 4; j++)
                    acc[i][j] += qv[i].x * kv[j].x + qv[i].y * kv[j].y
                               + qv[i].z * kv[j].z + qv[i].w * kv[j].w;
        }
#pragma unroll
        for (int i = 0; i < 4; i++)
#pragma unroll
            for (int j = 0; j < 4; j++)
                Ss[(ty + 16 * i) * LDSS + tx + 16 * j] = acc[i][j] * 0.0625f;
        __syncthreads();

        // Online softmax on row rr; this thread handles cols qq*16..qq*16+15.
        // The 4 threads of a row are consecutive lanes -> shfl_xor 1,2 combine.
        float tmax = -1e30f;
#pragma unroll
        for (int j = 0; j < 16; j++)
            tmax = fmaxf(tmax, Ss[rr * LDSS + qq * 16 + j]);
        tmax = fmaxf(tmax, __shfl_xor_sync(0xffffffffu, tmax, 1));
        tmax = fmaxf(tmax, __shfl_xor_sync(0xffffffffu, tmax, 2));

        float mnew  = fmaxf(mrow, tmax);
        float alpha = __expf(mrow - mnew);
        float psum  = 0.f;
#pragma unroll
        for (int j = 0; j < 16; j++) {
            float p = __expf(Ss[rr * LDSS + qq * 16 + j] - mnew);
            Ss[rr * LDSS + qq * 16 + j] = p;
            psum += p;
        }
        psum += __shfl_xor_sync(0xffffffffu, psum, 1);
        psum += __shfl_xor_sync(0xffffffffu, psum, 2);
        lrow = lrow * alpha + psum;
        mrow = mnew;
        __syncthreads();

        // O = O*alpha + P @ V  (thread owns row rr, cols c0..c0+63)
#pragma unroll
        for (int i = 0; i < 64; i++) o[i] *= alpha;
        for (int j = 0; j < KTILE; j++) {
            float p = Ss[rr * LDSS + j];
#pragma unroll
            for (int i4 = 0; i4 < 16; i4++) {
                float4 v = *(const float4*)&Vs[j * LDQ + c0 + i4 * 4];
                o[i4 * 4 + 0] += p * v.x;
                o[i4 * 4 + 1] += p * v.y;
                o[i4 * 4 + 2] += p * v.z;
                o[i4 * 4 + 3] += p * v.w;
            }
        }
    }

    const float inv = 1.f / lrow;
    float* og = out + ((size_t)b * Ssz + q0 + rr) * Dsz + c0;
#pragma unroll
    for (int i4 = 0; i4 < 16; i4++) {
        float4 v;
        v.x = o[i4 * 4 + 0] * inv;
        v.y = o[i4 * 4 + 1] * inv;
        v.z = o[i4 * 4 + 2] * inv;
        v.w = o[i4 * 4 + 3] * inv;
        *(float4*)(og + i4 * 4) = v;
    }
}

// ---------------------------------------------------------------------------
extern "C" void kernel_launch(void* const* d_in, const int* in_sizes, int n_in,
                              void* d_out, int out_size)
{
    const float* x  = (const float*)d_in[0];
    const float* Wq = (const float*)d_in[1];
    const float* bq = (const float*)d_in[2];
    const float* Wk = (const float*)d_in[3];
    const float* bk = (const float*)d_in[4];
    const float* Wv = (const float*)d_in[5];
    const float* bv = (const float*)d_in[6];
    float* out = (float*)d_out;

    cudaFuncSetAttribute(attn_kernel,
                         cudaFuncAttributeMaxDynamicSharedMemorySize,
                         ATTN_SMEM_BYTES);

    dim3 pg(Bsz * Ssz / PBM, Dsz / PBN, 3);
    qkv_proj_kernel<<<pg, 256>>>(x, Wq, bq, Wk, bk, Wv, bv);

    dim3 ag(Ssz / QTILE, Bsz);
    attn_kernel<<<ag, 256, ATTN_SMEM_BYTES>>>(out);
}